// round 1
// baseline (speedup 1.0000x reference)
#include <cuda_runtime.h>

#define N_NODES 8192
#define FEAT    256

// Scratch: __device__ globals (no allocations allowed in kernel_launch).
__device__ float g_d[N_NODES];                 // rsqrt of row degree
__device__ float g_supp[N_NODES * FEAT];       // d[k] * (input @ weight)[k,:]

// ---------------------------------------------------------------------------
// Kernel 1: d[i] = rsqrt(1 + sum_j adj[i][j])   (identity folded in as +1)
// One block per row, 256 threads, float4 loads.
// ---------------------------------------------------------------------------
__global__ __launch_bounds__(256)
void rowsum_rsqrt_kernel(const float* __restrict__ adj) {
    const int row = blockIdx.x;
    const float4* rp = reinterpret_cast<const float4*>(adj + (size_t)row * N_NODES);
    float s = 0.0f;
    #pragma unroll 4
    for (int i = threadIdx.x; i < N_NODES / 4; i += blockDim.x) {
        float4 v = __ldg(rp + i);
        s += (v.x + v.y) + (v.z + v.w);
    }
    // warp reduce
    #pragma unroll
    for (int o = 16; o > 0; o >>= 1) s += __shfl_down_sync(0xffffffffu, s, o);
    __shared__ float red[8];
    const int lane = threadIdx.x & 31;
    const int w    = threadIdx.x >> 5;
    if (lane == 0) red[w] = s;
    __syncthreads();
    if (w == 0) {
        s = (lane < 8) ? red[lane] : 0.0f;
        #pragma unroll
        for (int o = 4; o > 0; o >>= 1) s += __shfl_down_sync(0xffffffffu, s, o);
        if (lane == 0) g_d[row] = rsqrtf(s + 1.0f);
    }
}

// ---------------------------------------------------------------------------
// Tiled SGEMM, 128x128 block tile, BK=16, 256 threads, 8x8 microtile.
// MODE 0: C = d[i] * (A @ B)           A=input [M,256], B=weight [256,256]
//         -> writes g_supp
// MODE 1: out = d[i]*(A @ g_supp + g_supp[i,:]) + bias
//         A=adj [M,8192]  (identity term of a=adj+I folded into epilogue)
// N is always 256, ld of A is K, ld of B/C is 256.
// ---------------------------------------------------------------------------
#define BM 128
#define BN 128
#define BK 16
#define TM 8
#define TN 8

template <int MODE>
__global__ __launch_bounds__(256, 2)
void gemm_kernel(const float* __restrict__ A,
                 const float* __restrict__ B,     // used in MODE 0 only
                 float* __restrict__ C,           // used in MODE 1 only
                 const float* __restrict__ bias,  // used in MODE 1 only
                 int K) {
    __shared__ float As[BK][BM];
    __shared__ float Bs[BK][BN];

    const int tid     = threadIdx.x;
    const int rowBase = blockIdx.y * BM;
    const int colBase = blockIdx.x * BN;
    const int ty = tid >> 4;        // 0..15
    const int tx = tid & 15;        // 0..15

    // A-tile load mapping: 128x16 floats, float4 along k
    const int aRow  = tid >> 2;          // 0..63
    const int aCol  = (tid & 3) << 2;    // 0,4,8,12
    // B-tile load mapping: 16x128 floats, float4 along n
    const int bRow  = tid >> 5;          // 0..7
    const int bCol  = (tid & 31) << 2;   // 0..124

    const float* Bsrc = (MODE == 0) ? B : g_supp;

    float acc[TM][TN];
    #pragma unroll
    for (int m = 0; m < TM; m++)
        #pragma unroll
        for (int n = 0; n < TN; n++) acc[m][n] = 0.0f;

    for (int k0 = 0; k0 < K; k0 += BK) {
        // load A tile (transposed into As[k][m])
        #pragma unroll
        for (int r = 0; r < BM; r += 64) {
            float4 v = *reinterpret_cast<const float4*>(
                A + (size_t)(rowBase + aRow + r) * K + (k0 + aCol));
            As[aCol + 0][aRow + r] = v.x;
            As[aCol + 1][aRow + r] = v.y;
            As[aCol + 2][aRow + r] = v.z;
            As[aCol + 3][aRow + r] = v.w;
        }
        // load B tile
        #pragma unroll
        for (int r = 0; r < BK; r += 8) {
            *reinterpret_cast<float4*>(&Bs[bRow + r][bCol]) =
                *reinterpret_cast<const float4*>(
                    Bsrc + (size_t)(k0 + bRow + r) * FEAT + (colBase + bCol));
        }
        __syncthreads();

        #pragma unroll
        for (int k = 0; k < BK; k++) {
            float a[TM], b[TN];
            *reinterpret_cast<float4*>(&a[0]) = *reinterpret_cast<const float4*>(&As[k][ty * TM]);
            *reinterpret_cast<float4*>(&a[4]) = *reinterpret_cast<const float4*>(&As[k][ty * TM + 4]);
            *reinterpret_cast<float4*>(&b[0]) = *reinterpret_cast<const float4*>(&Bs[k][tx * TN]);
            *reinterpret_cast<float4*>(&b[4]) = *reinterpret_cast<const float4*>(&Bs[k][tx * TN + 4]);
            #pragma unroll
            for (int m = 0; m < TM; m++)
                #pragma unroll
                for (int n = 0; n < TN; n++)
                    acc[m][n] = fmaf(a[m], b[n], acc[m][n]);
        }
        __syncthreads();
    }

    // epilogue
    #pragma unroll
    for (int m = 0; m < TM; m++) {
        const int gr = rowBase + ty * TM + m;
        const float dr = g_d[gr];
        #pragma unroll
        for (int n4 = 0; n4 < TN; n4 += 4) {
            const int gc = colBase + tx * TN + n4;
            float4 o;
            if (MODE == 0) {
                o.x = dr * acc[m][n4 + 0];
                o.y = dr * acc[m][n4 + 1];
                o.z = dr * acc[m][n4 + 2];
                o.w = dr * acc[m][n4 + 3];
                *reinterpret_cast<float4*>(g_supp + (size_t)gr * FEAT + gc) = o;
            } else {
                float4 sv = *reinterpret_cast<const float4*>(g_supp + (size_t)gr * FEAT + gc);
                float4 bv = *reinterpret_cast<const float4*>(bias + gc);
                o.x = fmaf(dr, acc[m][n4 + 0] + sv.x, bv.x);
                o.y = fmaf(dr, acc[m][n4 + 1] + sv.y, bv.y);
                o.z = fmaf(dr, acc[m][n4 + 2] + sv.z, bv.z);
                o.w = fmaf(dr, acc[m][n4 + 3] + sv.w, bv.w);
                *reinterpret_cast<float4*>(C + (size_t)gr * FEAT + gc) = o;
            }
        }
    }
}

extern "C" void kernel_launch(void* const* d_in, const int* in_sizes, int n_in,
                              void* d_out, int out_size) {
    const float* input  = (const float*)d_in[0];   // [8192, 256]
    const float* adj    = (const float*)d_in[1];   // [8192, 8192]
    const float* weight = (const float*)d_in[2];   // [256, 256]
    const float* bias   = (const float*)d_in[3];   // [256]
    float* out = (float*)d_out;                    // [8192, 256]

    // 1) degree -> rsqrt
    rowsum_rsqrt_kernel<<<N_NODES, 256>>>(adj);

    // 2) g_supp = d[k] * (input @ weight)
    {
        dim3 grid(FEAT / BN, N_NODES / BM);
        gemm_kernel<0><<<grid, 256>>>(input, weight, nullptr, nullptr, FEAT);
    }

    // 3) out = d[i]*(adj @ g_supp + g_supp[i,:]) + bias
    {
        dim3 grid(FEAT / BN, N_NODES / BM);
        gemm_kernel<1><<<grid, 256>>>(adj, nullptr, out, bias, N_NODES);
    }
}

// round 3
// speedup vs baseline: 3.3057x; 3.3057x over previous
#include <cuda_runtime.h>
#include <cstdint>

#define N_NODES 8192
#define FEAT    256

// ---------------------------------------------------------------------------
// Device scratch
// ---------------------------------------------------------------------------
__device__ __align__(128) float g_d[N_NODES];            // rsqrt degree
__device__ __align__(128) float g_supp[N_NODES * FEAT];  // tf32-rounded d_k*(X W)

// ---------------------------------------------------------------------------
// helpers
// ---------------------------------------------------------------------------
__device__ __forceinline__ uint32_t smem_to_u32(const void* p) {
    uint32_t a;
    asm("{ .reg .u64 t; cvta.to.shared.u64 t, %1; cvt.u32.u64 %0, t; }" : "=r"(a) : "l"(p));
    return a;
}
__device__ __forceinline__ uint32_t f2tf32(float f) {
    uint32_t u;
    asm("cvt.rna.tf32.f32 %0, %1;" : "=r"(u) : "f"(f));
    return u;
}
#define CP_ASYNC_CG(smem, gptr) \
    asm volatile("cp.async.cg.shared.global [%0], [%1], 16;" :: "r"((uint32_t)(smem)), "l"(gptr) : "memory")
#define CP_COMMIT() asm volatile("cp.async.commit_group;" ::: "memory")
#define CP_WAIT2()  asm volatile("cp.async.wait_group 2;" ::: "memory")

__device__ __forceinline__ void mma_tf32(float* c, const uint32_t* a, const uint32_t* b) {
    asm volatile(
        "mma.sync.aligned.m16n8k8.row.col.f32.tf32.tf32.f32 "
        "{%0,%1,%2,%3}, {%4,%5,%6,%7}, {%8,%9}, {%0,%1,%2,%3};"
        : "+f"(c[0]), "+f"(c[1]), "+f"(c[2]), "+f"(c[3])
        : "r"(a[0]), "r"(a[1]), "r"(a[2]), "r"(a[3]), "r"(b[0]), "r"(b[1]));
}

// ---------------------------------------------------------------------------
// Kernel 1: d[i] = rsqrt(1 + sum_j adj[i][j])
// ---------------------------------------------------------------------------
__global__ __launch_bounds__(256)
void rowsum_rsqrt_kernel(const float* __restrict__ adj) {
    const int row = blockIdx.x;
    const float4* rp = reinterpret_cast<const float4*>(adj + (size_t)row * N_NODES);
    float s = 0.0f;
    #pragma unroll 4
    for (int i = threadIdx.x; i < N_NODES / 4; i += blockDim.x) {
        float4 v = __ldg(rp + i);
        s += (v.x + v.y) + (v.z + v.w);
    }
    #pragma unroll
    for (int o = 16; o > 0; o >>= 1) s += __shfl_down_sync(0xffffffffu, s, o);
    __shared__ float red[8];
    const int lane = threadIdx.x & 31;
    const int w = threadIdx.x >> 5;
    if (lane == 0) red[w] = s;
    __syncthreads();
    if (w == 0) {
        s = (lane < 8) ? red[lane] : 0.0f;
        #pragma unroll
        for (int o = 4; o > 0; o >>= 1) s += __shfl_down_sync(0xffffffffu, s, o);
        if (lane == 0) g_d[row] = rsqrtf(s + 1.0f);
    }
}

// ---------------------------------------------------------------------------
// Kernel 2: g_supp = tf32_round( d[k] * (input @ weight) )   (K=256 fp32 SIMT)
// ---------------------------------------------------------------------------
#define BM 128
#define BN 128
#define BK 16
#define TM 8
#define TN 8

__global__ __launch_bounds__(256, 2)
void small_gemm_kernel(const float* __restrict__ A, const float* __restrict__ B) {
    __shared__ float As[BK][BM];
    __shared__ float Bs[BK][BN];
    const int tid = threadIdx.x;
    const int rowBase = blockIdx.y * BM;
    const int colBase = blockIdx.x * BN;
    const int ty = tid >> 4, tx = tid & 15;
    const int aRow = tid >> 2, aCol = (tid & 3) << 2;
    const int bRow = tid >> 5, bCol = (tid & 31) << 2;
    const int K = FEAT;

    float acc[TM][TN];
    #pragma unroll
    for (int m = 0; m < TM; m++)
        #pragma unroll
        for (int n = 0; n < TN; n++) acc[m][n] = 0.0f;

    for (int k0 = 0; k0 < K; k0 += BK) {
        #pragma unroll
        for (int r = 0; r < BM; r += 64) {
            float4 v = *reinterpret_cast<const float4*>(A + (size_t)(rowBase + aRow + r) * K + (k0 + aCol));
            As[aCol + 0][aRow + r] = v.x; As[aCol + 1][aRow + r] = v.y;
            As[aCol + 2][aRow + r] = v.z; As[aCol + 3][aRow + r] = v.w;
        }
        #pragma unroll
        for (int r = 0; r < BK; r += 8)
            *reinterpret_cast<float4*>(&Bs[bRow + r][bCol]) =
                *reinterpret_cast<const float4*>(B + (size_t)(k0 + bRow + r) * FEAT + (colBase + bCol));
        __syncthreads();
        #pragma unroll
        for (int k = 0; k < BK; k++) {
            float a[TM], b[TN];
            *reinterpret_cast<float4*>(&a[0]) = *reinterpret_cast<const float4*>(&As[k][ty * TM]);
            *reinterpret_cast<float4*>(&a[4]) = *reinterpret_cast<const float4*>(&As[k][ty * TM + 4]);
            *reinterpret_cast<float4*>(&b[0]) = *reinterpret_cast<const float4*>(&Bs[k][tx * TN]);
            *reinterpret_cast<float4*>(&b[4]) = *reinterpret_cast<const float4*>(&Bs[k][tx * TN + 4]);
            #pragma unroll
            for (int m = 0; m < TM; m++)
                #pragma unroll
                for (int n = 0; n < TN; n++) acc[m][n] = fmaf(a[m], b[n], acc[m][n]);
        }
        __syncthreads();
    }
    #pragma unroll
    for (int m = 0; m < TM; m++) {
        const int gr = rowBase + ty * TM + m;
        const float dr = g_d[gr];
        #pragma unroll
        for (int n = 0; n < TN; n++) {
            const int gc = colBase + tx * TN + n;
            g_supp[(size_t)gr * FEAT + gc] = __uint_as_float(f2tf32(dr * acc[m][n]));
        }
    }
}

// ---------------------------------------------------------------------------
// Kernel 3: out = d_i * (adj @ g_supp + g_supp[i,:]) + bias
// TF32 mma.sync m16n8k8, CTA 128x128, 4 warps (warp tile 64x64),
// K-step 32, 4-stage cp.async pipeline.
// ---------------------------------------------------------------------------
#define SA 36                         // A smem row stride (floats), conflict-free
#define SB 136                        // B smem row stride (floats), conflict-free
#define STAGE_FLOATS (128 * SA + 32 * SB)       // 8960
#define STAGE_BYTES  (STAGE_FLOATS * 4)         // 35840
#define NSTAGES 4
#define MAIN_SMEM (NSTAGES * STAGE_BYTES)       // 143360
#define NITER (N_NODES / 32)                    // 256

__global__ __launch_bounds__(128, 1)
void gcn_main_gemm(const float* __restrict__ adj,
                   float* __restrict__ out,
                   const float* __restrict__ bias) {
    extern __shared__ float smem[];
    const uint32_t sb_u32 = smem_to_u32(smem);

    const int tid = threadIdx.x;
    const int wid = tid >> 5;
    const int lane = tid & 31;
    const int gid = lane >> 2;      // 0..7
    const int tig = lane & 3;       // 0..3
    const int wm = wid >> 1;        // 0..1  (64-row band)
    const int wn = wid & 1;         // 0..1  (64-col band)

    const int mBase = blockIdx.y * 128;
    const int nBase = blockIdx.x * 128;

    const float* Abase = adj + (size_t)mBase * N_NODES;
    const float* Bbase = g_supp + nBase;

    float acc[4][8][4];
    #pragma unroll
    for (int mt = 0; mt < 4; mt++)
        #pragma unroll
        for (int nt = 0; nt < 8; nt++)
            #pragma unroll
            for (int c = 0; c < 4; c++) acc[mt][nt][c] = 0.0f;

    // cp.async load of one K-stage (A: 128x32, B: 32x128)
    auto load_stage = [&](int s) {
        const int slot = s & (NSTAGES - 1);
        const uint32_t a_s = sb_u32 + slot * STAGE_BYTES;
        const uint32_t b_s = a_s + 128 * SA * 4;
        const float* ag = Abase + s * 32;
        const float* bg = Bbase + (size_t)(s * 32) * FEAT;
        #pragma unroll
        for (int i = 0; i < 8; i++) {            // A: 1024 16B granules
            const int g = tid + i * 128;
            const int r = g >> 3, q = g & 7;
            CP_ASYNC_CG(a_s + (r * SA + q * 4) * 4, ag + (size_t)r * N_NODES + q * 4);
        }
        #pragma unroll
        for (int i = 0; i < 8; i++) {            // B: 1024 16B granules
            const int g = tid + i * 128;
            const int k = g >> 5, q = g & 31;
            CP_ASYNC_CG(b_s + (k * SB + q * 4) * 4, bg + (size_t)k * FEAT + q * 4);
        }
    };

    #pragma unroll
    for (int p = 0; p < 3; p++) { load_stage(p); CP_COMMIT(); }

    for (int s = 0; s < NITER; s++) {
        CP_WAIT2();
        __syncthreads();

        if (s + 3 < NITER) { load_stage(s + 3); }
        CP_COMMIT();

        const int slot = s & (NSTAGES - 1);
        const float* As = smem + slot * STAGE_FLOATS;
        const float* Bs = As + 128 * SA;

        #pragma unroll
        for (int k8 = 0; k8 < 4; k8++) {
            uint32_t a[4][4], b[8][2];
            const int kk = k8 * 8;
            #pragma unroll
            for (int mt = 0; mt < 4; mt++) {
                const int r = wm * 64 + mt * 16 + gid;
                a[mt][0] = f2tf32(As[r * SA + kk + tig]);
                a[mt][1] = f2tf32(As[(r + 8) * SA + kk + tig]);
                a[mt][2] = f2tf32(As[r * SA + kk + tig + 4]);
                a[mt][3] = f2tf32(As[(r + 8) * SA + kk + tig + 4]);
            }
            #pragma unroll
            for (int nt = 0; nt < 8; nt++) {
                const int n = wn * 64 + nt * 8 + gid;
                b[nt][0] = __float_as_uint(Bs[(kk + tig) * SB + n]);
                b[nt][1] = __float_as_uint(Bs[(kk + tig + 4) * SB + n]);
            }
            #pragma unroll
            for (int mt = 0; mt < 4; mt++)
                #pragma unroll
                for (int nt = 0; nt < 8; nt++)
                    mma_tf32(acc[mt][nt], a[mt], b[nt]);
        }
        __syncthreads();
    }

    // epilogue: out = d_i * (acc + supp_i) + bias
    #pragma unroll
    for (int mt = 0; mt < 4; mt++) {
        const int r0 = mBase + wm * 64 + mt * 16 + gid;
        const int r1 = r0 + 8;
        const float d0 = g_d[r0];
        const float d1 = g_d[r1];
        #pragma unroll
        for (int nt = 0; nt < 8; nt++) {
            const int col = nBase + wn * 64 + nt * 8 + tig * 2;
            const float2 bv = *reinterpret_cast<const float2*>(bias + col);
            const float2 s0 = *reinterpret_cast<const float2*>(g_supp + (size_t)r0 * FEAT + col);
            const float2 s1 = *reinterpret_cast<const float2*>(g_supp + (size_t)r1 * FEAT + col);
            float2 o0, o1;
            o0.x = fmaf(d0, acc[mt][nt][0] + s0.x, bv.x);
            o0.y = fmaf(d0, acc[mt][nt][1] + s0.y, bv.y);
            o1.x = fmaf(d1, acc[mt][nt][2] + s1.x, bv.x);
            o1.y = fmaf(d1, acc[mt][nt][3] + s1.y, bv.y);
            *reinterpret_cast<float2*>(out + (size_t)r0 * FEAT + col) = o0;
            *reinterpret_cast<float2*>(out + (size_t)r1 * FEAT + col) = o1;
        }
    }
}

// ---------------------------------------------------------------------------
extern "C" void kernel_launch(void* const* d_in, const int* in_sizes, int n_in,
                              void* d_out, int out_size) {
    const float* input  = (const float*)d_in[0];   // [8192, 256]
    const float* adj    = (const float*)d_in[1];   // [8192, 8192]
    const float* weight = (const float*)d_in[2];   // [256, 256]
    const float* bias   = (const float*)d_in[3];   // [256]
    float* out = (float*)d_out;

    cudaFuncSetAttribute(gcn_main_gemm, cudaFuncAttributeMaxDynamicSharedMemorySize, MAIN_SMEM);

    rowsum_rsqrt_kernel<<<N_NODES, 256>>>(adj);
    {
        dim3 grid(FEAT / BN, N_NODES / BM);
        small_gemm_kernel<<<grid, 256>>>(input, weight);
    }
    {
        dim3 grid(FEAT / 128, N_NODES / 128);   // (2, 64)
        gcn_main_gemm<<<grid, 128, MAIN_SMEM>>>(adj, out, bias);
    }
}